// round 13
// baseline (speedup 1.0000x reference)
#include <cuda_runtime.h>
#include <math.h>
#include <float.h>

#define XS 2048
#define NN 4096
#define ZS 64
#define DD 6208
#define NV4 1552          // DD/4
#define TK 16
#define ZTK 8
#define EPSF 1e-9f
#define RNDF 0.5f
#define NCHUNK 64         // 32 rows per chunk
#define MIXBLK 128        // NCHUNK * 2 column-halves
#define HALF4 776         // NV4/2
#define YBLK 16
#define NCAND (YBLK * (TK + 1))   // 272

// k_post block roles (R10 topology)
#define B_RED0   0        // 7 blocks: mix_x reduce
#define B_DOTS   7        // 1 block: dots (waits c_red==7)
#define B_YC0    8        // 16 blocks: y candidates + y-range init
#define B_Z      24       // z init + top-9 + finals
#define B_XM     25       // x max -> inv_dx; age copy row XS-1
#define B_YM     26       // y merge (waits c_yc==16)
#define B_MYZ0   27       // 7 blocks: mix_y/mix_z (waits c_y && c_z)
#define B_XU0    34       // 512 blocks: x updates (waits c_dots && c_x)
#define B_YZ0    546      // 24 blocks: yz updates (waits c_myz==7)
#define NPOST    570

typedef unsigned long long u64;
typedef unsigned int u32;

// ---------------- device scratch (no allocations allowed) ----------------
__device__ __align__(16) float g_resp[DD];
__device__ __align__(16) float g_mix_x[DD];
__device__ __align__(16) float g_mix_y[DD];
__device__ __align__(16) float g_mix_z[DD];
__device__ float4 g_part4[NCHUNK][NV4];     // mix_x partials
__device__ u64   g_ckey[YBLK][TK + 1];
__device__ float g_yval[TK + 1];
__device__ int   g_yrow[TK + 1];
__device__ float g_zval[ZTK + 1];
__device__ int   g_zrow[ZTK + 1];
__device__ float g_inv_dx;
__device__ float g_dots[3];                 // |mix_x|^2, mix_x.inpt, |inpt|^2
// counters: used ONLY inside k_post; reset by k_main block 0
__device__ int c_red, c_dots, c_yc, c_y, c_z, c_x, c_myz;

// ---------------- helpers ----------------
__device__ __forceinline__ float blockReduceSumB(float v) {
    __shared__ float red[32];
    __shared__ float bcast;
    int lane = threadIdx.x & 31;
    int wid  = threadIdx.x >> 5;
    int nw   = blockDim.x >> 5;
#pragma unroll
    for (int o = 16; o > 0; o >>= 1) v += __shfl_down_sync(0xffffffffu, v, o);
    if (lane == 0) red[wid] = v;
    __syncthreads();
    if (wid == 0) {
        float x = (lane < nw) ? red[lane] : 0.0f;
#pragma unroll
        for (int o = 16; o > 0; o >>= 1) x += __shfl_down_sync(0xffffffffu, x, o);
        if (lane == 0) bcast = x;
    }
    __syncthreads();
    return bcast;
}

__device__ __forceinline__ u64 makeKey(float v, int row) {
    u32 u = __float_as_uint(v);
    u = (u & 0x80000000u) ? ~u : (u | 0x80000000u);
    return ((u64)u << 32) | (u32)(~row);
}
__device__ __forceinline__ float keyVal(u64 k) {
    u32 u = (u32)(k >> 32);
    u32 bits = (u & 0x80000000u) ? (u ^ 0x80000000u) : ~u;
    return __uint_as_float(bits);
}
__device__ __forceinline__ int keyRow(u64 k) { return (int)~((u32)k); }

// inline input vector: select from x / y_response / z
__device__ __forceinline__ float4 inpt4(int c4, const float4* __restrict__ x4,
                                        const float4* __restrict__ y4,
                                        const float4* __restrict__ z4) {
    if (c4 < 512)  return __ldg(x4 + c4);
    if (c4 < 1536) return __ldg(y4 + (c4 - 512));
    return __ldg(z4 + (c4 - 1536));
}

__device__ __forceinline__ void signalCnt(int* c) {
    __threadfence();
    __syncthreads();
    if (threadIdx.x == 0) atomicAdd(c, 1);
}
__device__ __forceinline__ void waitCnt(int* c, int target) {
    if (threadIdx.x == 0) {
        while (atomicAdd(c, 0) < target) __nanosleep(64);
    }
    __syncthreads();
}

// ---------------- K1: mixx partials (0..127) + matvec/copy (128..) ----------------
__global__ void k_main(const float4* __restrict__ neu4, const float* __restrict__ ages,
                       const float4* __restrict__ x4, const float4* __restrict__ y4,
                       const float4* __restrict__ z4, float* __restrict__ out_neu) {
    int t = threadIdx.x;
    int b = blockIdx.x;

    if (b == 0 && t == 0) {
        // reset k_post's counters (previous replay's k_post is stream-complete)
        c_red = 0; c_dots = 0; c_yc = 0; c_y = 0; c_z = 0; c_x = 0; c_myz = 0;
    }

    if (b < MIXBLK) {
        // ---- mix_x partials: chunk of 32 rows, one column half ----
        int chunk = b >> 1;
        int half  = b & 1;
        int r0 = chunk * 32;
        int r1 = min(r0 + 32, XS - 1);
        int cbase = half * HALF4;
        float4 acc0 = {0,0,0,0}, acc1 = {0,0,0,0}, acc2 = {0,0,0,0}, acc3 = {0,0,0,0};
        int c0 = cbase + t;
        int c1 = cbase + 256 + t;
        int c2 = cbase + 512 + t;
        int c3 = cbase + 768 + t;
        bool v3 = (768 + t) < HALF4;
#pragma unroll 1
        for (int r = r0; r < r1; r++) {
            float ag = __ldg(&ages[r]);
            float w = (ag - 1.0f) / ag;
            const float4* rowp = neu4 + (size_t)r * NV4;
            float4 a  = __ldg(rowp + c0);
            float4 bq = __ldg(rowp + c1);
            float4 cq = __ldg(rowp + c2);
            float4 dq = v3 ? __ldg(rowp + c3) : make_float4(0, 0, 0, 0);
            acc0.x = fmaf(w, a.x, acc0.x);  acc0.y = fmaf(w, a.y, acc0.y);
            acc0.z = fmaf(w, a.z, acc0.z);  acc0.w = fmaf(w, a.w, acc0.w);
            acc1.x = fmaf(w, bq.x, acc1.x); acc1.y = fmaf(w, bq.y, acc1.y);
            acc1.z = fmaf(w, bq.z, acc1.z); acc1.w = fmaf(w, bq.w, acc1.w);
            acc2.x = fmaf(w, cq.x, acc2.x); acc2.y = fmaf(w, cq.y, acc2.y);
            acc2.z = fmaf(w, cq.z, acc2.z); acc2.w = fmaf(w, cq.w, acc2.w);
            acc3.x = fmaf(w, dq.x, acc3.x); acc3.y = fmaf(w, dq.y, acc3.y);
            acc3.z = fmaf(w, dq.z, acc3.z); acc3.w = fmaf(w, dq.w, acc3.w);
        }
        g_part4[chunk][c0] = acc0;
        g_part4[chunk][c1] = acc1;
        g_part4[chunk][c2] = acc2;
        if (v3) g_part4[chunk][c3] = acc3;
        return;
    }

    // ---- matvec row + fused copy (skip rows < XS-1, rewritten later) ----
    int row = b - MIXBLK;
    const float4* src = neu4 + (size_t)row * NV4;
    float4* dst = reinterpret_cast<float4*>(out_neu) + (size_t)row * NV4;
    float acc = 0.0f;
    bool docopy = (row >= XS - 1);
    if (docopy) {
#pragma unroll
        for (int j = 0; j < 7; j++) {
            int c = t + j * 256;
            if (c < NV4) {
                float4 v = __ldcs(src + c);        // single-use: evict-first
                float4 w = inpt4(c, x4, y4, z4);
                acc = fmaf(v.x, w.x, acc);
                acc = fmaf(v.y, w.y, acc);
                acc = fmaf(v.z, w.z, acc);
                acc = fmaf(v.w, w.w, acc);
                __stcs(dst + c, v);
            }
        }
    } else {
#pragma unroll
        for (int j = 0; j < 7; j++) {
            int c = t + j * 256;
            if (c < NV4) {
                float4 v = __ldg(src + c);         // read twice (mixx): keep in L2
                float4 w = inpt4(c, x4, y4, z4);
                acc = fmaf(v.x, w.x, acc);
                acc = fmaf(v.y, w.y, acc);
                acc = fmaf(v.z, w.z, acc);
                acc = fmaf(v.w, w.w, acc);
            }
        }
    }
    float tot = blockReduceSumB(acc);
    if (t == 0) g_resp[row] = tot;
}

// ---------------- K2: reduce/dots + selection + init-work + mixes + row updates ----------------
__global__ void k_post(const float* __restrict__ ages, const float4* __restrict__ neu4,
                       const float4* __restrict__ x4, const float4* __restrict__ y4,
                       const float4* __restrict__ z4,
                       float* __restrict__ out_z, float* __restrict__ out_final,
                       float* __restrict__ out_ages, float* __restrict__ out_neu) {
    int t = threadIdx.x;      // 0..255
    int b = blockIdx.x;

    // ======== x update blocks (bulk of work) ========
    if (b >= B_XU0 && b < B_YZ0) {
        waitCnt(&c_dots, 1);
        waitCnt(&c_x, 1);
        int r0 = (b - B_XU0) * 4;
        float invdx = g_inv_dx;
        float dxx = g_dots[0], dxi = g_dots[1], dii = g_dots[2];
        if (b == B_YZ0 - 1 && t == 0)
            out_final[XS - 1] = g_resp[XS - 1] * invdx;   // last x row: final only
        const float4* mxp = reinterpret_cast<const float4*>(g_mix_x);
#pragma unroll 1
        for (int rr = 0; rr < 4; rr++) {
            int r = r0 + rr;
            if (r >= XS - 1) break;   // uniform across block
            float a = __ldg(&ages[r]);
            float rsp = g_resp[r];
            if (t == 0) {
                out_final[r] = rsp * invdx;
                out_ages[r]  = a + 1.0f;
            }
            float s = rsp * invdx / a;
            float ssq = dxx + 2.0f * s * dxi + s * s * dii;
            float inv = 1.0f / (sqrtf(ssq) + 1e-12f);
            float si = s * inv;
            float4* dst = reinterpret_cast<float4*>(out_neu) + (size_t)r * NV4;
#pragma unroll
            for (int j = 0; j < 7; j++) {
                int c4 = t + j * 256;
                if (c4 < NV4) {
                    float4 iv = inpt4(c4, x4, y4, z4), mv = mxp[c4];
                    float4 o;
                    o.x = fmaf(si, iv.x, mv.x * inv);
                    o.y = fmaf(si, iv.y, mv.y * inv);
                    o.z = fmaf(si, iv.z, mv.z * inv);
                    o.w = fmaf(si, iv.w, mv.w * inv);
                    __stcs(dst + c4, o);
                }
            }
        }
        return;
    }

    // ======== yz update blocks ========
    if (b >= B_YZ0) {
        waitCnt(&c_myz, 7);
        int bb = b - B_YZ0;
        int r; float val; const float4* mix;
        if (bb < TK) { r = g_yrow[bb]; val = g_yval[bb]; mix = reinterpret_cast<const float4*>(g_mix_y); }
        else         { r = g_zrow[bb - TK]; val = g_zval[bb - TK]; mix = reinterpret_cast<const float4*>(g_mix_z); }
        float s = val / __ldg(&ages[r]);
        float4 v[7];
        float ssq = 0.0f;
#pragma unroll
        for (int j = 0; j < 7; j++) {
            int c4 = t + j * 256;
            if (c4 < NV4) {
                float4 iv = inpt4(c4, x4, y4, z4), mv = mix[c4];
                float4 vv;
                vv.x = fmaf(s, iv.x, mv.x);
                vv.y = fmaf(s, iv.y, mv.y);
                vv.z = fmaf(s, iv.z, mv.z);
                vv.w = fmaf(s, iv.w, mv.w);
                v[j] = vv;
                ssq = fmaf(vv.x, vv.x, ssq);
                ssq = fmaf(vv.y, vv.y, ssq);
                ssq = fmaf(vv.z, vv.z, ssq);
                ssq = fmaf(vv.w, vv.w, ssq);
            }
        }
        float tot = blockReduceSumB(ssq);
        float inv = 1.0f / (sqrtf(tot) + 1e-12f);
        float4* dst = reinterpret_cast<float4*>(out_neu) + (size_t)r * NV4;
#pragma unroll
        for (int j = 0; j < 7; j++) {
            int c4 = t + j * 256;
            if (c4 < NV4) {
                float4 o = v[j];
                o.x *= inv; o.y *= inv; o.z *= inv; o.w *= inv;
                __stcs(dst + c4, o);
            }
        }
        return;
    }

    // ======== producer / selection blocks ========
    if (b < B_DOTS) {
        // ---- mix_x reduce (g_part4 ready via stream order) ----
        int c4 = b * 256 + t;
        if (c4 < NV4) {
            float4 mx = {0, 0, 0, 0};
#pragma unroll
            for (int ch = 0; ch < NCHUNK; ch++) {
                float4 p = g_part4[ch][c4];
                mx.x += p.x; mx.y += p.y; mx.z += p.z; mx.w += p.w;
            }
            reinterpret_cast<float4*>(g_mix_x)[c4] = mx;
        }
        signalCnt(&c_red);
        return;
    }

    if (b == B_DOTS) {
        waitCnt(&c_red, 7);
        const float4* mx4 = reinterpret_cast<const float4*>(g_mix_x);
        float dxx = 0.0f, dxi = 0.0f, dii = 0.0f;
        for (int c4 = t; c4 < NV4; c4 += 256) {
            float4 m = mx4[c4];
            float4 p = inpt4(c4, x4, y4, z4);
            dxx = fmaf(m.x, m.x, dxx); dxx = fmaf(m.y, m.y, dxx);
            dxx = fmaf(m.z, m.z, dxx); dxx = fmaf(m.w, m.w, dxx);
            dxi = fmaf(m.x, p.x, dxi); dxi = fmaf(m.y, p.y, dxi);
            dxi = fmaf(m.z, p.z, dxi); dxi = fmaf(m.w, p.w, dxi);
            dii = fmaf(p.x, p.x, dii); dii = fmaf(p.y, p.y, dii);
            dii = fmaf(p.z, p.z, dii); dii = fmaf(p.w, p.w, dii);
        }
        float sxx = blockReduceSumB(dxx);
        float sxi = blockReduceSumB(dxi);
        float sii = blockReduceSumB(dii);
        if (t == 0) { g_dots[0] = sxx; g_dots[1] = sxi; g_dots[2] = sii; }
        signalCnt(&c_dots);
        return;
    }

    if (b >= B_YC0 && b < B_Z) {
        // ---- y candidates + y-range init (zero final / copy ages) ----
        __shared__ u64 sk[256];
        int w = b - B_YC0;
        int row = XS + w * 256 + t;
        out_final[row] = 0.0f;
        out_ages[row]  = __ldg(&ages[row]);
        u64 key = makeKey(g_resp[row], row);
        sk[t] = key;
        __syncthreads();
        int rank = 0;
#pragma unroll 8
        for (int j = 0; j < 256; j++) rank += (sk[j] > key);
        if (rank < TK + 1) g_ckey[w][rank] = key;
        signalCnt(&c_yc);
        return;
    }

    if (b == B_Z) {
        // ---- z range init + z top-9 + finals ----
        __shared__ u64   zk[ZS];
        __shared__ float s_zv[ZTK + 1];
        __shared__ int   s_zr[ZTK + 1];
        if (t < ZS) {
            int row = XS + NN + t;
            out_z[t] = 0.0f;
            out_final[row] = 0.0f;
            out_ages[row]  = __ldg(&ages[row]);
            zk[t] = makeKey(g_resp[row], row);
        }
        __syncthreads();
        if (t < ZS) {
            u64 key = zk[t];
            int rank = 0;
#pragma unroll
            for (int j = 0; j < ZS; j++) rank += (zk[j] > key);
            if (rank < ZTK + 1) {
                float v = keyVal(key); int row = keyRow(key);
                s_zv[rank] = v; s_zr[rank] = row;
                g_zval[rank] = v; g_zrow[rank] = row;
            }
        }
        __syncthreads();
        if (t < ZTK) {
            float zvL = s_zv[ZTK];
            float dz = 1.0f / (s_zv[0] - zvL);
            int r = s_zr[t];
            float f = (s_zv[t] - zvL) * dz;
            out_final[r] = f;
            out_z[r - (XS + NN)] = f;
            out_ages[r] = __ldg(&ages[r]) + 1.0f;
        }
        signalCnt(&c_z);
        return;
    }

    if (b == B_XM) {
        // ---- x max + nonzero -> g_inv_dx; age copy row XS-1 ----
        __shared__ float s_xv[8];
        __shared__ int   s_xnz[8];
        int lane = t & 31;
        int wid  = t >> 5;
        if (t == 0) out_ages[XS - 1] = __ldg(&ages[XS - 1]);
        float bv = -FLT_MAX; int nz = 0;
#pragma unroll
        for (int j = 0; j < 8; j++) {
            float v = g_resp[t + j * 256];
            bv = fmaxf(bv, v);
            nz |= (v != 0.0f);
        }
#pragma unroll
        for (int o = 16; o > 0; o >>= 1) {
            bv  = fmaxf(bv, __shfl_down_sync(0xffffffffu, bv, o));
            nz |= __shfl_down_sync(0xffffffffu, nz, o);
        }
        if (lane == 0) { s_xv[wid] = bv; s_xnz[wid] = nz; }
        __syncthreads();
        if (t == 0) {
            float m = s_xv[0]; int z2 = s_xnz[0];
#pragma unroll
            for (int w2 = 1; w2 < 8; w2++) { m = fmaxf(m, s_xv[w2]); z2 |= s_xnz[w2]; }
            float tx = z2 ? 0.0f : 1.0f;
            g_inv_dx = 1.0f / (m + EPSF * tx * RNDF);
        }
        signalCnt(&c_x);
        return;
    }

    if (b == B_YM) {
        // ---- y merge: rank over 272 candidates + finals ----
        __shared__ u64   s_k[NCAND];
        __shared__ float s_yv[TK + 1];
        __shared__ int   s_yr[TK + 1];
        waitCnt(&c_yc, YBLK);
        s_k[t] = ((const u64*)g_ckey)[t];
        if (t < NCAND - 256) s_k[256 + t] = ((const u64*)g_ckey)[256 + t];
        __syncthreads();
#pragma unroll 1
        for (int pass = 0; pass < 2; pass++) {
            int idx = t + pass * 256;
            if (idx < NCAND) {
                u64 key = s_k[idx];
                int rank = 0;
#pragma unroll 8
                for (int j = 0; j < NCAND; j++) rank += (s_k[j] > key);
                if (rank < TK + 1) {
                    float v = keyVal(key); int row = keyRow(key);
                    s_yv[rank] = v; s_yr[rank] = row;
                    g_yval[rank] = v; g_yrow[rank] = row;
                }
            }
        }
        __syncthreads();
        if (t < 32) {
            float yvL = s_yv[TK];
            bool tie = (t < TK) && (s_yv[t] == yvL);
            u32 bal = __ballot_sync(0xffffffffu, tie);
            float ty = bal ? 1.0f : 0.0f;
            if (t < TK) {
                float dy = 1.0f / (s_yv[0] - yvL + EPSF * ty * RNDF);
                int r = s_yr[t];
                out_final[r] = (s_yv[t] - yvL) * dy;
                out_ages[r]  = __ldg(&ages[r]) + 1.0f;
            }
        }
        signalCnt(&c_y);
        return;
    }

    // ---- b in B_MYZ0..B_MYZ0+6: mix_y / mix_z ----
    {
        waitCnt(&c_y, 1);
        waitCnt(&c_z, 1);
        int c4 = (b - B_MYZ0) * 256 + t;
        if (c4 < NV4) {
            float4 my = {0, 0, 0, 0};
#pragma unroll
            for (int k = 0; k < TK; k++) {
                int r = g_yrow[k];
                float ag = __ldg(&ages[r]);
                float w = (ag - 1.0f) / ag;
                float4 v = __ldg(&neu4[(size_t)r * NV4 + c4]);
                my.x = fmaf(w, v.x, my.x); my.y = fmaf(w, v.y, my.y);
                my.z = fmaf(w, v.z, my.z); my.w = fmaf(w, v.w, my.w);
            }
            reinterpret_cast<float4*>(g_mix_y)[c4] = my;

            float4 mz = {0, 0, 0, 0};
#pragma unroll
            for (int k = 0; k < ZTK; k++) {
                int r = g_zrow[k];
                float ag = __ldg(&ages[r]);
                float w = (ag - 1.0f) / ag;
                float4 v = __ldg(&neu4[(size_t)r * NV4 + c4]);
                mz.x = fmaf(w, v.x, mz.x); mz.y = fmaf(w, v.y, mz.y);
                mz.z = fmaf(w, v.z, mz.z); mz.w = fmaf(w, v.w, mz.w);
            }
            reinterpret_cast<float4*>(g_mix_z)[c4] = mz;
        }
        signalCnt(&c_myz);
        return;
    }
}

// ---------------- launch ----------------
extern "C" void kernel_launch(void* const* d_in, const int* in_sizes, int n_in,
                              void* d_out, int out_size) {
    (void)in_sizes; (void)n_in; (void)out_size;
    const float* x       = (const float*)d_in[0];
    const float* z       = (const float*)d_in[1];
    const float* yresp   = (const float*)d_in[2];
    const float* neurons = (const float*)d_in[3];
    const float* ages    = (const float*)d_in[4];

    float* out       = (float*)d_out;
    float* out_z     = out;                                // 64
    float* out_final = out + ZS;                           // 6208
    float* out_neu   = out + ZS + DD;                      // 6208*6208
    float* out_ages  = out + ZS + DD + (size_t)DD * DD;    // 6208

    k_main<<<MIXBLK + DD, 256>>>((const float4*)neurons, ages,
                                 (const float4*)x, (const float4*)yresp, (const float4*)z,
                                 out_neu);
    k_post<<<NPOST, 256>>>(ages, (const float4*)neurons,
                           (const float4*)x, (const float4*)yresp, (const float4*)z,
                           out_z, out_final, out_ages, out_neu);
}

// round 14
// speedup vs baseline: 1.0477x; 1.0477x over previous
#include <cuda_runtime.h>
#include <math.h>
#include <float.h>

#define XS 2048
#define NN 4096
#define ZS 64
#define DD 6208
#define NV4 1552          // DD/4
#define TK 16
#define ZTK 8
#define EPSF 1e-9f
#define RNDF 0.5f
#define NCHUNK 256        // 8 rows per chunk
#define MIXBLK 512        // NCHUNK * 2 column-halves
#define HALF4 776         // NV4/2
#define YBLK 16
#define NCAND (YBLK * (TK + 1))   // 272

// k_main: blocks [0,512) mixx+rowdots, [512, 512+4161) matvec rows 2047..6207
#define MVROWS 4161
#define NMAIN (MIXBLK + MVROWS)

// k_post block roles (R10 topology)
#define B_RED0   0        // 7 blocks: mix_x reduce
#define B_DOTS   7        // 1 block: dots (waits c_red==7)
#define B_YC0    8        // 16 blocks: y candidates
#define B_Z      24       // z top-9 + finals
#define B_XM     25       // x resp assembly + max -> inv_dx
#define B_YM     26       // y merge (waits c_yc==16)
#define B_MYZ0   27       // 7 blocks: mix_y/mix_z (waits c_y && c_z)
#define B_XU0    34       // 512 blocks: x updates (waits c_dots && c_x)
#define B_YZ0    546      // 24 blocks: yz updates (waits c_myz==7)
#define NPOST    570

typedef unsigned long long u64;
typedef unsigned int u32;

// ---------------- device scratch (no allocations allowed) ----------------
__device__ __align__(16) float g_inpt[DD];
__device__ float g_w[DD];                   // (ages-1)/ages
__device__ __align__(16) float g_resp[DD];
__device__ __align__(16) float g_mix_x[DD];
__device__ __align__(16) float g_mix_y[DD];
__device__ __align__(16) float g_mix_z[DD];
__device__ float4 g_part4[NCHUNK][NV4];     // mix_x partials (6.35 MB)
__device__ float  g_rdot[NCHUNK][2][8];     // per-(chunk,half) row-dot partials
__device__ u64   g_ckey[YBLK][TK + 1];
__device__ float g_yval[TK + 1];
__device__ int   g_yrow[TK + 1];
__device__ float g_zval[ZTK + 1];
__device__ int   g_zrow[ZTK + 1];
__device__ float g_inv_dx;
__device__ float g_dots[3];                 // |mix_x|^2, mix_x.inpt, |inpt|^2
__device__ int c_red, c_dots, c_yc, c_y, c_z, c_x, c_myz;

// ---------------- helpers ----------------
__device__ __forceinline__ float blockReduceSumB(float v) {
    __shared__ float red[32];
    __shared__ float bcast;
    int lane = threadIdx.x & 31;
    int wid  = threadIdx.x >> 5;
    int nw   = blockDim.x >> 5;
#pragma unroll
    for (int o = 16; o > 0; o >>= 1) v += __shfl_down_sync(0xffffffffu, v, o);
    if (lane == 0) red[wid] = v;
    __syncthreads();
    if (wid == 0) {
        float x = (lane < nw) ? red[lane] : 0.0f;
#pragma unroll
        for (int o = 16; o > 0; o >>= 1) x += __shfl_down_sync(0xffffffffu, x, o);
        if (lane == 0) bcast = x;
    }
    __syncthreads();
    return bcast;
}

__device__ __forceinline__ u64 makeKey(float v, int row) {
    u32 u = __float_as_uint(v);
    u = (u & 0x80000000u) ? ~u : (u | 0x80000000u);
    return ((u64)u << 32) | (u32)(~row);
}
__device__ __forceinline__ float keyVal(u64 k) {
    u32 u = (u32)(k >> 32);
    u32 bits = (u & 0x80000000u) ? (u ^ 0x80000000u) : ~u;
    return __uint_as_float(bits);
}
__device__ __forceinline__ int keyRow(u64 k) { return (int)~((u32)k); }

__device__ __forceinline__ void signalCnt(int* c) {
    __threadfence();
    __syncthreads();
    if (threadIdx.x == 0) atomicAdd(c, 1);
}
__device__ __forceinline__ void waitCnt(int* c, int target) {
    if (threadIdx.x == 0) {
        while (atomicAdd(c, 0) < target) __nanosleep(64);
    }
    __syncthreads();
}

// ---------------- K1: build inpt, weights, zero final, copy ages, reset ctrs ----------------
__global__ void k_init(const float* __restrict__ x, const float* __restrict__ z,
                       const float* __restrict__ yresp, const float* __restrict__ ages,
                       float* __restrict__ out_z, float* __restrict__ out_final,
                       float* __restrict__ out_ages) {
    int i = blockIdx.x * 256 + threadIdx.x;
    if (i < DD) {
        float v;
        if (i < XS)           v = x[i];
        else if (i < XS + NN) v = yresp[i - XS];
        else                  v = z[i - XS - NN];
        g_inpt[i] = v;
        float a = ages[i];
        g_w[i] = (a - 1.0f) / a;
        out_final[i] = 0.0f;
        out_ages[i]  = a;
    }
    if (i < ZS) out_z[i] = 0.0f;
    if (i == 0) { c_red = 0; c_dots = 0; c_yc = 0; c_y = 0; c_z = 0; c_x = 0; c_myz = 0; }
}

// ---------------- K2: mixx+rowdots (blocks 0..511) + matvec/copy (rows 2047+) ----------------
__global__ void k_main(const float4* __restrict__ neu4, float* __restrict__ out_neu) {
    int t = threadIdx.x;
    int b = blockIdx.x;
    const float4* ip = reinterpret_cast<const float4*>(g_inpt);

    if (b < MIXBLK) {
        // ---- 8 rows, one column half: column partials + per-row dots ----
        __shared__ float sdot[8][264];
        int chunk = b >> 1;
        int half  = b & 1;
        int r0 = chunk * 8;
        int nrows = min(8, (XS - 1) - r0);   // 8 except last chunk (7)
        int cbase = half * HALF4;
        int c0 = cbase + t;
        int c1 = cbase + 256 + t;
        int c2 = cbase + 512 + t;
        int c3 = cbase + 768 + t;
        bool v3 = (768 + t) < HALF4;
        float4 i0 = ip[c0];
        float4 i1 = ip[c1];
        float4 i2 = ip[c2];
        float4 i3 = v3 ? ip[c3] : make_float4(0, 0, 0, 0);
        float4 acc0 = {0,0,0,0}, acc1 = {0,0,0,0}, acc2 = {0,0,0,0}, acc3 = {0,0,0,0};
        float dot[8];
#pragma unroll
        for (int rr = 0; rr < 8; rr++) {
            dot[rr] = 0.0f;
            if (rr < nrows) {
                int r = r0 + rr;
                float w = g_w[r];
                const float4* rowp = neu4 + (size_t)r * NV4;
                float4 a  = __ldg(rowp + c0);
                float4 bq = __ldg(rowp + c1);
                float4 cq = __ldg(rowp + c2);
                float4 dq = v3 ? __ldg(rowp + c3) : make_float4(0, 0, 0, 0);
                acc0.x = fmaf(w, a.x, acc0.x);  acc0.y = fmaf(w, a.y, acc0.y);
                acc0.z = fmaf(w, a.z, acc0.z);  acc0.w = fmaf(w, a.w, acc0.w);
                acc1.x = fmaf(w, bq.x, acc1.x); acc1.y = fmaf(w, bq.y, acc1.y);
                acc1.z = fmaf(w, bq.z, acc1.z); acc1.w = fmaf(w, bq.w, acc1.w);
                acc2.x = fmaf(w, cq.x, acc2.x); acc2.y = fmaf(w, cq.y, acc2.y);
                acc2.z = fmaf(w, cq.z, acc2.z); acc2.w = fmaf(w, cq.w, acc2.w);
                acc3.x = fmaf(w, dq.x, acc3.x); acc3.y = fmaf(w, dq.y, acc3.y);
                acc3.z = fmaf(w, dq.z, acc3.z); acc3.w = fmaf(w, dq.w, acc3.w);
                float d = 0.0f;
                d = fmaf(a.x,  i0.x, d); d = fmaf(a.y,  i0.y, d);
                d = fmaf(a.z,  i0.z, d); d = fmaf(a.w,  i0.w, d);
                d = fmaf(bq.x, i1.x, d); d = fmaf(bq.y, i1.y, d);
                d = fmaf(bq.z, i1.z, d); d = fmaf(bq.w, i1.w, d);
                d = fmaf(cq.x, i2.x, d); d = fmaf(cq.y, i2.y, d);
                d = fmaf(cq.z, i2.z, d); d = fmaf(cq.w, i2.w, d);
                d = fmaf(dq.x, i3.x, d); d = fmaf(dq.y, i3.y, d);
                d = fmaf(dq.z, i3.z, d); d = fmaf(dq.w, i3.w, d);
                dot[rr] = d;
            }
        }
        g_part4[chunk][c0] = acc0;
        g_part4[chunk][c1] = acc1;
        g_part4[chunk][c2] = acc2;
        if (v3) g_part4[chunk][c3] = acc3;
        // one-shot row-dot reduction: smem stage + 8 parallel warp reduces
#pragma unroll
        for (int rr = 0; rr < 8; rr++) sdot[rr][t] = dot[rr];
        __syncthreads();
        int wid = t >> 5, lane = t & 31;
        float s = 0.0f;
#pragma unroll
        for (int k = 0; k < 8; k++) s += sdot[wid][lane + k * 32];
#pragma unroll
        for (int o = 16; o > 0; o >>= 1) s += __shfl_down_sync(0xffffffffu, s, o);
        if (lane == 0 && wid < nrows) g_rdot[chunk][half][wid] = s;
        return;
    }

    // ---- matvec row + fused copy for rows 2047..6207 ----
    int row = (XS - 1) + (b - MIXBLK);
    const float4* src = neu4 + (size_t)row * NV4;
    float4* dst = reinterpret_cast<float4*>(out_neu) + (size_t)row * NV4;
    float acc = 0.0f;
#pragma unroll
    for (int j = 0; j < 7; j++) {
        int c = t + j * 256;
        if (c < NV4) {
            float4 v = __ldg(src + c);
            float4 w = ip[c];
            acc = fmaf(v.x, w.x, acc);
            acc = fmaf(v.y, w.y, acc);
            acc = fmaf(v.z, w.z, acc);
            acc = fmaf(v.w, w.w, acc);
            __stcs(dst + c, v);
        }
    }
    float tot = blockReduceSumB(acc);
    if (t == 0) g_resp[row] = tot;
}

// ---------------- K3: reduce/dots + selection + mixes + all row updates ----------------
__global__ void k_post(const float* __restrict__ ages, const float4* __restrict__ neu4,
                       float* __restrict__ out_z, float* __restrict__ out_final,
                       float* __restrict__ out_ages, float* __restrict__ out_neu) {
    int t = threadIdx.x;      // 0..255
    int b = blockIdx.x;
    const float4* ip = reinterpret_cast<const float4*>(g_inpt);

    // ======== x update blocks (bulk of work) ========
    if (b >= B_XU0 && b < B_YZ0) {
        waitCnt(&c_dots, 1);
        waitCnt(&c_x, 1);
        int r0 = (b - B_XU0) * 4;
        float invdx = g_inv_dx;
        float dxx = g_dots[0], dxi = g_dots[1], dii = g_dots[2];
        if (b == B_YZ0 - 1 && t == 0)
            out_final[XS - 1] = g_resp[XS - 1] * invdx;   // last x row: final only
        const float4* mxp = reinterpret_cast<const float4*>(g_mix_x);
#pragma unroll 1
        for (int rr = 0; rr < 4; rr++) {
            int r = r0 + rr;
            if (r >= XS - 1) break;   // uniform across block
            float a = __ldg(&ages[r]);
            float rsp = g_resp[r];
            if (t == 0) {
                out_final[r] = rsp * invdx;
                out_ages[r]  = a + 1.0f;
            }
            float s = rsp * invdx / a;
            float ssq = dxx + 2.0f * s * dxi + s * s * dii;
            float inv = 1.0f / (sqrtf(ssq) + 1e-12f);
            float si = s * inv;
            float4* dst = reinterpret_cast<float4*>(out_neu) + (size_t)r * NV4;
#pragma unroll
            for (int j = 0; j < 7; j++) {
                int c4 = t + j * 256;
                if (c4 < NV4) {
                    float4 iv = ip[c4], mv = mxp[c4];
                    float4 o;
                    o.x = fmaf(si, iv.x, mv.x * inv);
                    o.y = fmaf(si, iv.y, mv.y * inv);
                    o.z = fmaf(si, iv.z, mv.z * inv);
                    o.w = fmaf(si, iv.w, mv.w * inv);
                    __stcs(dst + c4, o);
                }
            }
        }
        return;
    }

    // ======== yz update blocks ========
    if (b >= B_YZ0) {
        waitCnt(&c_myz, 7);
        int bb = b - B_YZ0;
        int r; float val; const float4* mix;
        if (bb < TK) { r = g_yrow[bb]; val = g_yval[bb]; mix = reinterpret_cast<const float4*>(g_mix_y); }
        else         { r = g_zrow[bb - TK]; val = g_zval[bb - TK]; mix = reinterpret_cast<const float4*>(g_mix_z); }
        float s = val / __ldg(&ages[r]);
        float4 v[7];
        float ssq = 0.0f;
#pragma unroll
        for (int j = 0; j < 7; j++) {
            int c4 = t + j * 256;
            if (c4 < NV4) {
                float4 iv = ip[c4], mv = mix[c4];
                float4 vv;
                vv.x = fmaf(s, iv.x, mv.x);
                vv.y = fmaf(s, iv.y, mv.y);
                vv.z = fmaf(s, iv.z, mv.z);
                vv.w = fmaf(s, iv.w, mv.w);
                v[j] = vv;
                ssq = fmaf(vv.x, vv.x, ssq);
                ssq = fmaf(vv.y, vv.y, ssq);
                ssq = fmaf(vv.z, vv.z, ssq);
                ssq = fmaf(vv.w, vv.w, ssq);
            }
        }
        float tot = blockReduceSumB(ssq);
        float inv = 1.0f / (sqrtf(tot) + 1e-12f);
        float4* dst = reinterpret_cast<float4*>(out_neu) + (size_t)r * NV4;
#pragma unroll
        for (int j = 0; j < 7; j++) {
            int c4 = t + j * 256;
            if (c4 < NV4) {
                float4 o = v[j];
                o.x *= inv; o.y *= inv; o.z *= inv; o.w *= inv;
                __stcs(dst + c4, o);
            }
        }
        return;
    }

    // ======== producer / selection blocks ========
    if (b < B_DOTS) {
        // ---- mix_x reduce over 256 chunks ----
        int c4 = b * 256 + t;
        if (c4 < NV4) {
            float4 mx = {0, 0, 0, 0};
#pragma unroll 8
            for (int ch = 0; ch < NCHUNK; ch++) {
                float4 p = g_part4[ch][c4];
                mx.x += p.x; mx.y += p.y; mx.z += p.z; mx.w += p.w;
            }
            reinterpret_cast<float4*>(g_mix_x)[c4] = mx;
        }
        signalCnt(&c_red);
        return;
    }

    if (b == B_DOTS) {
        waitCnt(&c_red, 7);
        const float4* mx4 = reinterpret_cast<const float4*>(g_mix_x);
        float dxx = 0.0f, dxi = 0.0f, dii = 0.0f;
        for (int c4 = t; c4 < NV4; c4 += 256) {
            float4 m = mx4[c4];
            float4 p = ip[c4];
            dxx = fmaf(m.x, m.x, dxx); dxx = fmaf(m.y, m.y, dxx);
            dxx = fmaf(m.z, m.z, dxx); dxx = fmaf(m.w, m.w, dxx);
            dxi = fmaf(m.x, p.x, dxi); dxi = fmaf(m.y, p.y, dxi);
            dxi = fmaf(m.z, p.z, dxi); dxi = fmaf(m.w, p.w, dxi);
            dii = fmaf(p.x, p.x, dii); dii = fmaf(p.y, p.y, dii);
            dii = fmaf(p.z, p.z, dii); dii = fmaf(p.w, p.w, dii);
        }
        float sxx = blockReduceSumB(dxx);
        float sxi = blockReduceSumB(dxi);
        float sii = blockReduceSumB(dii);
        if (t == 0) { g_dots[0] = sxx; g_dots[1] = sxi; g_dots[2] = sii; }
        signalCnt(&c_dots);
        return;
    }

    if (b >= B_YC0 && b < B_Z) {
        // ---- y candidates: key-rank over 256 ----
        __shared__ u64 sk[256];
        int w = b - B_YC0;
        int row = XS + w * 256 + t;
        u64 key = makeKey(g_resp[row], row);
        sk[t] = key;
        __syncthreads();
        int rank = 0;
#pragma unroll 8
        for (int j = 0; j < 256; j++) rank += (sk[j] > key);
        if (rank < TK + 1) g_ckey[w][rank] = key;
        signalCnt(&c_yc);
        return;
    }

    if (b == B_Z) {
        __shared__ u64   zk[ZS];
        __shared__ float s_zv[ZTK + 1];
        __shared__ int   s_zr[ZTK + 1];
        if (t < ZS) {
            int row = XS + NN + t;
            zk[t] = makeKey(g_resp[row], row);
        }
        __syncthreads();
        if (t < ZS) {
            u64 key = zk[t];
            int rank = 0;
#pragma unroll
            for (int j = 0; j < ZS; j++) rank += (zk[j] > key);
            if (rank < ZTK + 1) {
                float v = keyVal(key); int row = keyRow(key);
                s_zv[rank] = v; s_zr[rank] = row;
                g_zval[rank] = v; g_zrow[rank] = row;
            }
        }
        __syncthreads();
        if (t < ZTK) {
            float zvL = s_zv[ZTK];
            float dz = 1.0f / (s_zv[0] - zvL);
            int r = s_zr[t];
            float f = (s_zv[t] - zvL) * dz;
            out_final[r] = f;
            out_z[r - (XS + NN)] = f;
            out_ages[r] = __ldg(&ages[r]) + 1.0f;
        }
        signalCnt(&c_z);
        return;
    }

    if (b == B_XM) {
        // ---- assemble g_resp[0..2046] from half-partials; x max -> g_inv_dx ----
        __shared__ float s_xv[8];
        __shared__ int   s_xnz[8];
        int lane = t & 31;
        int wid  = t >> 5;
        float bv = -FLT_MAX; int nz = 0;
#pragma unroll
        for (int j = 0; j < 8; j++) {
            int r = t + j * 256;
            float v;
            if (r < XS - 1) {
                v = g_rdot[r >> 3][0][r & 7] + g_rdot[r >> 3][1][r & 7];
                g_resp[r] = v;
            } else {
                v = g_resp[XS - 1];
            }
            bv = fmaxf(bv, v);
            nz |= (v != 0.0f);
        }
#pragma unroll
        for (int o = 16; o > 0; o >>= 1) {
            bv  = fmaxf(bv, __shfl_down_sync(0xffffffffu, bv, o));
            nz |= __shfl_down_sync(0xffffffffu, nz, o);
        }
        if (lane == 0) { s_xv[wid] = bv; s_xnz[wid] = nz; }
        __syncthreads();
        if (t == 0) {
            float m = s_xv[0]; int z2 = s_xnz[0];
#pragma unroll
            for (int w2 = 1; w2 < 8; w2++) { m = fmaxf(m, s_xv[w2]); z2 |= s_xnz[w2]; }
            float tx = z2 ? 0.0f : 1.0f;
            g_inv_dx = 1.0f / (m + EPSF * tx * RNDF);
        }
        signalCnt(&c_x);
        return;
    }

    if (b == B_YM) {
        __shared__ u64   s_k[NCAND];
        __shared__ float s_yv[TK + 1];
        __shared__ int   s_yr[TK + 1];
        waitCnt(&c_yc, YBLK);
        s_k[t] = ((const u64*)g_ckey)[t];
        if (t < NCAND - 256) s_k[256 + t] = ((const u64*)g_ckey)[256 + t];
        __syncthreads();
#pragma unroll 1
        for (int pass = 0; pass < 2; pass++) {
            int idx = t + pass * 256;
            if (idx < NCAND) {
                u64 key = s_k[idx];
                int rank = 0;
#pragma unroll 8
                for (int j = 0; j < NCAND; j++) rank += (s_k[j] > key);
                if (rank < TK + 1) {
                    float v = keyVal(key); int row = keyRow(key);
                    s_yv[rank] = v; s_yr[rank] = row;
                    g_yval[rank] = v; g_yrow[rank] = row;
                }
            }
        }
        __syncthreads();
        if (t < 32) {
            float yvL = s_yv[TK];
            bool tie = (t < TK) && (s_yv[t] == yvL);
            u32 bal = __ballot_sync(0xffffffffu, tie);
            float ty = bal ? 1.0f : 0.0f;
            if (t < TK) {
                float dy = 1.0f / (s_yv[0] - yvL + EPSF * ty * RNDF);
                int r = s_yr[t];
                out_final[r] = (s_yv[t] - yvL) * dy;
                out_ages[r]  = __ldg(&ages[r]) + 1.0f;
            }
        }
        signalCnt(&c_y);
        return;
    }

    // ---- b in B_MYZ0..B_MYZ0+6: mix_y / mix_z ----
    {
        waitCnt(&c_y, 1);
        waitCnt(&c_z, 1);
        int c4 = (b - B_MYZ0) * 256 + t;
        if (c4 < NV4) {
            float4 my = {0, 0, 0, 0};
#pragma unroll
            for (int k = 0; k < TK; k++) {
                int r = g_yrow[k];
                float w = g_w[r];
                float4 v = __ldg(&neu4[(size_t)r * NV4 + c4]);
                my.x = fmaf(w, v.x, my.x); my.y = fmaf(w, v.y, my.y);
                my.z = fmaf(w, v.z, my.z); my.w = fmaf(w, v.w, my.w);
            }
            reinterpret_cast<float4*>(g_mix_y)[c4] = my;

            float4 mz = {0, 0, 0, 0};
#pragma unroll
            for (int k = 0; k < ZTK; k++) {
                int r = g_zrow[k];
                float w = g_w[r];
                float4 v = __ldg(&neu4[(size_t)r * NV4 + c4]);
                mz.x = fmaf(w, v.x, mz.x); mz.y = fmaf(w, v.y, mz.y);
                mz.z = fmaf(w, v.z, mz.z); mz.w = fmaf(w, v.w, mz.w);
            }
            reinterpret_cast<float4*>(g_mix_z)[c4] = mz;
        }
        signalCnt(&c_myz);
        return;
    }
}

// ---------------- launch ----------------
extern "C" void kernel_launch(void* const* d_in, const int* in_sizes, int n_in,
                              void* d_out, int out_size) {
    (void)in_sizes; (void)n_in; (void)out_size;
    const float* x       = (const float*)d_in[0];
    const float* z       = (const float*)d_in[1];
    const float* yresp   = (const float*)d_in[2];
    const float* neurons = (const float*)d_in[3];
    const float* ages    = (const float*)d_in[4];

    float* out       = (float*)d_out;
    float* out_z     = out;                                // 64
    float* out_final = out + ZS;                           // 6208
    float* out_neu   = out + ZS + DD;                      // 6208*6208
    float* out_ages  = out + ZS + DD + (size_t)DD * DD;    // 6208

    k_init<<<(DD + 255) / 256, 256>>>(x, z, yresp, ages, out_z, out_final, out_ages);
    k_main<<<NMAIN, 256>>>((const float4*)neurons, out_neu);
    k_post<<<NPOST, 256>>>(ages, (const float4*)neurons,
                           out_z, out_final, out_ages, out_neu);
}

// round 16
// speedup vs baseline: 1.1959x; 1.1415x over previous
#include <cuda_runtime.h>
#include <math.h>
#include <float.h>

#define XS 2048
#define NN 4096
#define ZS 64
#define DD 6208
#define NV4 1552          // DD/4
#define TK 16
#define ZTK 8
#define EPSF 1e-9f
#define RNDF 0.5f
#define NCHUNK 64         // 32 rows per chunk
#define MIXBLK 128        // NCHUNK * 2 column-halves
#define HALF4 776         // NV4/2
#define YBLK 16
#define NCAND (YBLK * (TK + 1))   // 272

// k_post block roles (R10 topology)
#define B_RED0   0        // 7 blocks: mix_x reduce
#define B_DOTS   7        // 1 block: dots (waits c_red==7)
#define B_YC0    8        // 16 blocks: y candidates
#define B_Z      24       // z top-9 + finals
#define B_XM     25       // x max -> inv_dx
#define B_YM     26       // y merge (waits c_yc==16)
#define B_MYZ0   27       // 7 blocks: mix_y/mix_z (waits c_y && c_z)
#define B_XU0    34       // 512 blocks: x updates (waits c_dots && c_x)
#define B_YZ0    546      // 24 blocks: yz updates (waits c_myz==7)
#define NPOST    570

typedef unsigned long long u64;
typedef unsigned int u32;

// ---------------- device scratch (no allocations allowed) ----------------
__device__ __align__(16) float g_inpt[DD];
__device__ float g_w[DD];                 // (ages-1)/ages
__device__ __align__(16) float g_resp[DD];
__device__ __align__(16) float g_mix_x[DD];
__device__ __align__(16) float g_mix_y[DD];
__device__ __align__(16) float g_mix_z[DD];
__device__ float4 g_part4[NCHUNK][NV4];   // deterministic partial sums
__device__ u64   g_ckey[YBLK][TK + 1];    // per-block sorted y candidate keys
__device__ float g_yval[TK + 1];
__device__ int   g_yrow[TK + 1];
__device__ float g_zval[ZTK + 1];
__device__ int   g_zrow[ZTK + 1];
__device__ float g_inv_dx;
__device__ float g_dots[3];               // |mix_x|^2, mix_x.inpt, |inpt|^2
__device__ int c_red, c_dots, c_yc, c_y, c_z, c_x, c_myz;

// ---------------- PDL helpers ----------------
__device__ __forceinline__ void pdlWait() {
    asm volatile("griddepcontrol.wait;" ::: "memory");
}
__device__ __forceinline__ void pdlLaunchDeps() {
    asm volatile("griddepcontrol.launch_dependents;" ::: "memory");
}

// ---------------- helpers ----------------
__device__ __forceinline__ float blockReduceSumB(float v) {
    __shared__ float red[32];
    __shared__ float bcast;
    int lane = threadIdx.x & 31;
    int wid  = threadIdx.x >> 5;
    int nw   = blockDim.x >> 5;
#pragma unroll
    for (int o = 16; o > 0; o >>= 1) v += __shfl_down_sync(0xffffffffu, v, o);
    if (lane == 0) red[wid] = v;
    __syncthreads();
    if (wid == 0) {
        float x = (lane < nw) ? red[lane] : 0.0f;
#pragma unroll
        for (int o = 16; o > 0; o >>= 1) x += __shfl_down_sync(0xffffffffu, x, o);
        if (lane == 0) bcast = x;
    }
    __syncthreads();
    return bcast;
}

__device__ __forceinline__ u64 makeKey(float v, int row) {
    u32 u = __float_as_uint(v);
    u = (u & 0x80000000u) ? ~u : (u | 0x80000000u);
    return ((u64)u << 32) | (u32)(~row);
}
__device__ __forceinline__ float keyVal(u64 k) {
    u32 u = (u32)(k >> 32);
    u32 bits = (u & 0x80000000u) ? (u ^ 0x80000000u) : ~u;
    return __uint_as_float(bits);
}
__device__ __forceinline__ int keyRow(u64 k) { return (int)~((u32)k); }

__device__ __forceinline__ void signalCnt(int* c) {
    __threadfence();
    __syncthreads();
    if (threadIdx.x == 0) atomicAdd(c, 1);
}
__device__ __forceinline__ void waitCnt(int* c, int target) {
    if (threadIdx.x == 0) {
        while (atomicAdd(c, 0) < target) __nanosleep(64);
    }
    __syncthreads();
}

// ---------------- K1: build inpt, weights, zero final/counters, copy ages ----------------
__global__ void k_init(const float* __restrict__ x, const float* __restrict__ z,
                       const float* __restrict__ yresp, const float* __restrict__ ages,
                       float* __restrict__ out_z, float* __restrict__ out_final,
                       float* __restrict__ out_ages) {
    int i = blockIdx.x * 256 + threadIdx.x;
    if (i < DD) {
        float v;
        if (i < XS)           v = x[i];
        else if (i < XS + NN) v = yresp[i - XS];
        else                  v = z[i - XS - NN];
        g_inpt[i] = v;
        float a = ages[i];
        g_w[i] = (a - 1.0f) / a;
        out_final[i] = 0.0f;
        out_ages[i]  = a;
    }
    if (i < ZS) out_z[i] = 0.0f;
    if (i == 0) { c_red = 0; c_dots = 0; c_yc = 0; c_y = 0; c_z = 0; c_x = 0; c_myz = 0; }
    pdlLaunchDeps();
}

// ---------------- K2: fused mixx partials (blocks 0..127) + matvec/copy ----------------
__global__ void k_main(const float4* __restrict__ neu4, float* __restrict__ out_neu) {
    pdlWait();    // k_init's g_inpt / g_w / counters visible
    int t = threadIdx.x;
    int b = blockIdx.x;

    if (b < MIXBLK) {
        int chunk = b >> 1;
        int half  = b & 1;
        int r0 = chunk * 32;
        int r1 = min(r0 + 32, XS - 1);
        int cbase = half * HALF4;
        float4 acc0 = {0,0,0,0}, acc1 = {0,0,0,0}, acc2 = {0,0,0,0}, acc3 = {0,0,0,0};
        int c0 = cbase + t;
        int c1 = cbase + 256 + t;
        int c2 = cbase + 512 + t;
        int c3 = cbase + 768 + t;
        bool v3 = (768 + t) < HALF4;
        for (int r = r0; r < r1; r++) {
            float w = g_w[r];
            const float4* rowp = neu4 + (size_t)r * NV4;
            float4 a = __ldg(rowp + c0);
            float4 bq = __ldg(rowp + c1);
            float4 cq = __ldg(rowp + c2);
            float4 dq = v3 ? __ldg(rowp + c3) : make_float4(0,0,0,0);
            acc0.x = fmaf(w, a.x, acc0.x);  acc0.y = fmaf(w, a.y, acc0.y);
            acc0.z = fmaf(w, a.z, acc0.z);  acc0.w = fmaf(w, a.w, acc0.w);
            acc1.x = fmaf(w, bq.x, acc1.x); acc1.y = fmaf(w, bq.y, acc1.y);
            acc1.z = fmaf(w, bq.z, acc1.z); acc1.w = fmaf(w, bq.w, acc1.w);
            acc2.x = fmaf(w, cq.x, acc2.x); acc2.y = fmaf(w, cq.y, acc2.y);
            acc2.z = fmaf(w, cq.z, acc2.z); acc2.w = fmaf(w, cq.w, acc2.w);
            acc3.x = fmaf(w, dq.x, acc3.x); acc3.y = fmaf(w, dq.y, acc3.y);
            acc3.z = fmaf(w, dq.z, acc3.z); acc3.w = fmaf(w, dq.w, acc3.w);
        }
        g_part4[chunk][c0] = acc0;
        g_part4[chunk][c1] = acc1;
        g_part4[chunk][c2] = acc2;
        if (v3) g_part4[chunk][c3] = acc3;
        pdlLaunchDeps();
        return;
    }

    int row = b - MIXBLK;
    const float4* src = neu4 + (size_t)row * NV4;
    float4* dst = reinterpret_cast<float4*>(out_neu) + (size_t)row * NV4;
    const float4* ip = reinterpret_cast<const float4*>(g_inpt);
    float acc = 0.0f;
    bool docopy = (row >= XS - 1);
#pragma unroll
    for (int j = 0; j < 7; j++) {
        int c = t + j * 256;
        if (c < NV4) {
            float4 v = __ldg(src + c);
            float4 w = ip[c];
            acc = fmaf(v.x, w.x, acc);
            acc = fmaf(v.y, w.y, acc);
            acc = fmaf(v.z, w.z, acc);
            acc = fmaf(v.w, w.w, acc);
            if (docopy) __stcs(dst + c, v);
        }
    }
    float tot = blockReduceSumB(acc);
    if (t == 0) g_resp[row] = tot;
    pdlLaunchDeps();
}

// ---------------- K3: single fused post-kernel (all selection + mixes + updates) ----------------
__global__ void k_post(const float* __restrict__ ages, const float4* __restrict__ neu4,
                       float* __restrict__ out_z, float* __restrict__ out_final,
                       float* __restrict__ out_ages, float* __restrict__ out_neu) {
    pdlWait();    // all of k_main's g_resp / g_part4 visible
    int t = threadIdx.x;      // 0..255
    int b = blockIdx.x;
    const float4* ip = reinterpret_cast<const float4*>(g_inpt);

    // ======== x update blocks (bulk of work) ========
    if (b >= B_XU0 && b < B_YZ0) {
        waitCnt(&c_dots, 1);
        waitCnt(&c_x, 1);
        int r0 = (b - B_XU0) * 4;
        float invdx = g_inv_dx;
        float dxx = g_dots[0], dxi = g_dots[1], dii = g_dots[2];
        if (b == B_YZ0 - 1 && t == 0)
            out_final[XS - 1] = g_resp[XS - 1] * invdx;   // last x row: final only
        const float4* mxp = reinterpret_cast<const float4*>(g_mix_x);
#pragma unroll 1
        for (int rr = 0; rr < 4; rr++) {
            int r = r0 + rr;
            if (r >= XS - 1) break;   // uniform across block
            float a = __ldg(&ages[r]);
            float rsp = g_resp[r];
            if (t == 0) {
                out_final[r] = rsp * invdx;
                out_ages[r]  = a + 1.0f;
            }
            float s = rsp * invdx / a;
            float ssq = dxx + 2.0f * s * dxi + s * s * dii;
            float inv = 1.0f / (sqrtf(ssq) + 1e-12f);
            float si = s * inv;
            float4* dst = reinterpret_cast<float4*>(out_neu) + (size_t)r * NV4;
#pragma unroll
            for (int j = 0; j < 7; j++) {
                int c4 = t + j * 256;
                if (c4 < NV4) {
                    float4 iv = ip[c4], mv = mxp[c4];
                    float4 o;
                    o.x = fmaf(si, iv.x, mv.x * inv);
                    o.y = fmaf(si, iv.y, mv.y * inv);
                    o.z = fmaf(si, iv.z, mv.z * inv);
                    o.w = fmaf(si, iv.w, mv.w * inv);
                    __stcs(dst + c4, o);
                }
            }
        }
        return;
    }

    // ======== yz update blocks ========
    if (b >= B_YZ0) {
        waitCnt(&c_myz, 7);
        int bb = b - B_YZ0;
        int r; float val; const float4* mix;
        if (bb < TK) { r = g_yrow[bb]; val = g_yval[bb]; mix = reinterpret_cast<const float4*>(g_mix_y); }
        else         { r = g_zrow[bb - TK]; val = g_zval[bb - TK]; mix = reinterpret_cast<const float4*>(g_mix_z); }
        float s = val / __ldg(&ages[r]);
        float4 v[7];
        float ssq = 0.0f;
#pragma unroll
        for (int j = 0; j < 7; j++) {
            int c4 = t + j * 256;
            if (c4 < NV4) {
                float4 iv = ip[c4], mv = mix[c4];
                float4 vv;
                vv.x = fmaf(s, iv.x, mv.x);
                vv.y = fmaf(s, iv.y, mv.y);
                vv.z = fmaf(s, iv.z, mv.z);
                vv.w = fmaf(s, iv.w, mv.w);
                v[j] = vv;
                ssq = fmaf(vv.x, vv.x, ssq);
                ssq = fmaf(vv.y, vv.y, ssq);
                ssq = fmaf(vv.z, vv.z, ssq);
                ssq = fmaf(vv.w, vv.w, ssq);
            }
        }
        float tot = blockReduceSumB(ssq);
        float inv = 1.0f / (sqrtf(tot) + 1e-12f);
        float4* dst = reinterpret_cast<float4*>(out_neu) + (size_t)r * NV4;
#pragma unroll
        for (int j = 0; j < 7; j++) {
            int c4 = t + j * 256;
            if (c4 < NV4) {
                float4 o = v[j];
                o.x *= inv; o.y *= inv; o.z *= inv; o.w *= inv;
                __stcs(dst + c4, o);
            }
        }
        return;
    }

    // ======== control / producer blocks ========
    if (b < B_DOTS) {
        // ---- mix_x reduce: 7 blocks over NV4 float4 columns ----
        int c4 = b * 256 + t;
        if (c4 < NV4) {
            float4 mx = {0, 0, 0, 0};
#pragma unroll
            for (int ch = 0; ch < NCHUNK; ch++) {
                float4 p = g_part4[ch][c4];
                mx.x += p.x; mx.y += p.y; mx.z += p.z; mx.w += p.w;
            }
            reinterpret_cast<float4*>(g_mix_x)[c4] = mx;
        }
        signalCnt(&c_red);
        return;
    }

    if (b == B_DOTS) {
        waitCnt(&c_red, 7);
        float dxx = 0.0f, dxi = 0.0f, dii = 0.0f;
        for (int i = t; i < DD; i += 256) {
            float m = g_mix_x[i];
            float p = g_inpt[i];
            dxx = fmaf(m, m, dxx);
            dxi = fmaf(m, p, dxi);
            dii = fmaf(p, p, dii);
        }
        float sxx = blockReduceSumB(dxx);
        float sxi = blockReduceSumB(dxi);
        float sii = blockReduceSumB(dii);
        if (t == 0) { g_dots[0] = sxx; g_dots[1] = sxi; g_dots[2] = sii; }
        signalCnt(&c_dots);
        return;
    }

    if (b >= B_YC0 && b < B_YC0 + YBLK) {
        // ---- y candidates: key-rank over 256 ----
        __shared__ u64 sk[256];
        int w = b - B_YC0;
        int row = XS + w * 256 + t;
        u64 key = makeKey(g_resp[row], row);
        sk[t] = key;
        __syncthreads();
        int rank = 0;
#pragma unroll 8
        for (int j = 0; j < 256; j++) rank += (sk[j] > key);
        if (rank < TK + 1) g_ckey[w][rank] = key;
        signalCnt(&c_yc);
        return;
    }

    if (b == B_Z) {
        // ---- z top-9 + z finals ----
        __shared__ u64   zk[ZS];
        __shared__ float s_zv[ZTK + 1];
        __shared__ int   s_zr[ZTK + 1];
        if (t < ZS) {
            int row = XS + NN + t;
            zk[t] = makeKey(g_resp[row], row);
        }
        __syncthreads();
        if (t < ZS) {
            u64 key = zk[t];
            int rank = 0;
#pragma unroll
            for (int j = 0; j < ZS; j++) rank += (zk[j] > key);
            if (rank < ZTK + 1) {
                float v = keyVal(key); int row = keyRow(key);
                s_zv[rank] = v; s_zr[rank] = row;
                g_zval[rank] = v; g_zrow[rank] = row;
            }
        }
        __syncthreads();
        if (t < ZTK) {
            float zvL = s_zv[ZTK];
            float dz = 1.0f / (s_zv[0] - zvL);
            int r = s_zr[t];
            float f = (s_zv[t] - zvL) * dz;
            out_final[r] = f;
            out_z[r - (XS + NN)] = f;
            out_ages[r] = ages[r] + 1.0f;
        }
        signalCnt(&c_z);
        return;
    }

    if (b == B_XM) {
        // ---- x max + nonzero -> g_inv_dx ----
        __shared__ float s_xv[8];
        __shared__ int   s_xnz[8];
        int lane = t & 31;
        int wid  = t >> 5;
        float bv = -FLT_MAX; int nz = 0;
#pragma unroll
        for (int j = 0; j < 8; j++) {
            float v = g_resp[t + j * 256];
            bv = fmaxf(bv, v);
            nz |= (v != 0.0f);
        }
#pragma unroll
        for (int o = 16; o > 0; o >>= 1) {
            bv  = fmaxf(bv, __shfl_down_sync(0xffffffffu, bv, o));
            nz |= __shfl_down_sync(0xffffffffu, nz, o);
        }
        if (lane == 0) { s_xv[wid] = bv; s_xnz[wid] = nz; }
        __syncthreads();
        if (t == 0) {
            float m = s_xv[0]; int z2 = s_xnz[0];
#pragma unroll
            for (int w2 = 1; w2 < 8; w2++) { m = fmaxf(m, s_xv[w2]); z2 |= s_xnz[w2]; }
            float tx = z2 ? 0.0f : 1.0f;
            g_inv_dx = 1.0f / (m + EPSF * tx * RNDF);
        }
        signalCnt(&c_x);
        return;
    }

    if (b == B_YM) {
        // ---- y merge: rank over 272 candidates (2 per thread) + finals ----
        __shared__ u64   s_k[NCAND];
        __shared__ float s_yv[TK + 1];
        __shared__ int   s_yr[TK + 1];
        waitCnt(&c_yc, YBLK);
        s_k[t] = ((const u64*)g_ckey)[t];
        if (t < NCAND - 256) s_k[256 + t] = ((const u64*)g_ckey)[256 + t];
        __syncthreads();
#pragma unroll 1
        for (int pass = 0; pass < 2; pass++) {
            int idx = t + pass * 256;
            if (idx < NCAND) {
                u64 key = s_k[idx];
                int rank = 0;
#pragma unroll 8
                for (int j = 0; j < NCAND; j++) rank += (s_k[j] > key);
                if (rank < TK + 1) {
                    float v = keyVal(key); int row = keyRow(key);
                    s_yv[rank] = v; s_yr[rank] = row;
                    g_yval[rank] = v; g_yrow[rank] = row;
                }
            }
        }
        __syncthreads();
        if (t < 32) {
            float yvL = s_yv[TK];
            bool tie = (t < TK) && (s_yv[t] == yvL);
            u32 bal = __ballot_sync(0xffffffffu, tie);
            float ty = bal ? 1.0f : 0.0f;
            if (t < TK) {
                float dy = 1.0f / (s_yv[0] - yvL + EPSF * ty * RNDF);
                int r = s_yr[t];
                out_final[r] = (s_yv[t] - yvL) * dy;
                out_ages[r]  = ages[r] + 1.0f;
            }
        }
        signalCnt(&c_y);
        return;
    }

    // ---- b in B_MYZ0..B_MYZ0+6: mix_y / mix_z ----
    {
        waitCnt(&c_y, 1);
        waitCnt(&c_z, 1);
        int c4 = (b - B_MYZ0) * 256 + t;
        if (c4 < NV4) {
            float4 my = {0, 0, 0, 0};
#pragma unroll
            for (int k = 0; k < TK; k++) {
                int r = g_yrow[k];
                float w = g_w[r];
                float4 v = __ldg(&neu4[(size_t)r * NV4 + c4]);
                my.x = fmaf(w, v.x, my.x); my.y = fmaf(w, v.y, my.y);
                my.z = fmaf(w, v.z, my.z); my.w = fmaf(w, v.w, my.w);
            }
            reinterpret_cast<float4*>(g_mix_y)[c4] = my;

            float4 mz = {0, 0, 0, 0};
#pragma unroll
            for (int k = 0; k < ZTK; k++) {
                int r = g_zrow[k];
                float w = g_w[r];
                float4 v = __ldg(&neu4[(size_t)r * NV4 + c4]);
                mz.x = fmaf(w, v.x, mz.x); mz.y = fmaf(w, v.y, mz.y);
                mz.z = fmaf(w, v.z, mz.z); mz.w = fmaf(w, v.w, mz.w);
            }
            reinterpret_cast<float4*>(g_mix_z)[c4] = mz;
        }
        signalCnt(&c_myz);
        return;
    }
}

// ---------------- launch ----------------
extern "C" void kernel_launch(void* const* d_in, const int* in_sizes, int n_in,
                              void* d_out, int out_size) {
    (void)in_sizes; (void)n_in; (void)out_size;
    const float* x       = (const float*)d_in[0];
    const float* z       = (const float*)d_in[1];
    const float* yresp   = (const float*)d_in[2];
    const float* neurons = (const float*)d_in[3];
    const float* ages    = (const float*)d_in[4];

    float* out       = (float*)d_out;
    float* out_z     = out;                                // 64
    float* out_final = out + ZS;                           // 6208
    float* out_neu   = out + ZS + DD;                      // 6208*6208
    float* out_ages  = out + ZS + DD + (size_t)DD * DD;    // 6208

    k_init<<<(DD + 255) / 256, 256>>>(x, z, yresp, ages, out_z, out_final, out_ages);

    // k_main with programmatic dependent launch (overlaps launch with k_init)
    {
        cudaLaunchConfig_t cfg = {};
        cfg.gridDim  = dim3(MIXBLK + DD, 1, 1);
        cfg.blockDim = dim3(256, 1, 1);
        cfg.stream   = 0;
        cudaLaunchAttribute attr[1];
        attr[0].id = cudaLaunchAttributeProgrammaticStreamSerialization;
        attr[0].val.programmaticStreamSerializationAllowed = 1;
        cfg.attrs = attr;
        cfg.numAttrs = 1;
        const float4* neu4 = (const float4*)neurons;
        cudaLaunchKernelEx(&cfg, k_main, neu4, out_neu);
    }

    // k_post with programmatic dependent launch (overlaps launch with k_main)
    {
        cudaLaunchConfig_t cfg = {};
        cfg.gridDim  = dim3(NPOST, 1, 1);
        cfg.blockDim = dim3(256, 1, 1);
        cfg.stream   = 0;
        cudaLaunchAttribute attr[1];
        attr[0].id = cudaLaunchAttributeProgrammaticStreamSerialization;
        attr[0].val.programmaticStreamSerializationAllowed = 1;
        cfg.attrs = attr;
        cfg.numAttrs = 1;
        const float4* neu4 = (const float4*)neurons;
        cudaLaunchKernelEx(&cfg, k_post, ages, neu4, out_z, out_final, out_ages, out_neu);
    }
}